// round 17
// baseline (speedup 1.0000x reference)
#include <cuda_runtime.h>
#include <cstdint>

#define N_TOK 16384
#define NHEAD 4
#define NCODE 1024
#define DH    256
#define EPS   4.0f

// fp32 norm tables (FROZEN: bitwise-matched to XLA reduction emitter)
__device__ float g_csq[NHEAD * NCODE];
__device__ float g_xsq[N_TOK * NHEAD];
__device__ int   g_idx[NHEAD * N_TOK];
// screen results
__device__ int   g_cand[NHEAD * N_TOK * 16];
__device__ int   g_cnt [NHEAD * N_TOK];

__device__ __forceinline__ float to_tf32(float v) {
    float o;
    asm("cvt.rna.tf32.f32 %0, %1;" : "=f"(o) : "f"(v));
    return o;
}

// ---- FROZEN: XLA warp tree 16,8,4,2,1 ----
__device__ __forceinline__ float warp_tree(float v) {
#pragma unroll
    for (int off = 16; off > 0; off >>= 1)
        v = __fadd_rn(v, __shfl_down_sync(0xFFFFFFFFu, v, off));
    return v;
}

// ---- FROZEN: XLA row sum-of-squares ----
__device__ __forceinline__ float rowsq_xla(const float* __restrict__ row, int lane) {
    float W[4];
#pragma unroll
    for (int w = 0; w < 4; w++) {
        int t = lane + 32 * w;
        float2 v = *(const float2*)(row + 2 * t);
        float m0 = __fmul_rn(v.x, v.x);
        float m1 = __fmul_rn(v.y, v.y);
        float a  = __fadd_rn(m0, m1);
        W[w] = warp_tree(a);
    }
    return __fadd_rn(__fadd_rn(W[0], W[2]), __fadd_rn(W[1], W[3]));
}

__global__ void csq_kernel(const float* __restrict__ cb) {
    int warp = (blockIdx.x * blockDim.x + threadIdx.x) >> 5;
    int lane = threadIdx.x & 31;
    if (warp >= NHEAD * NCODE) return;
    float s = rowsq_xla(cb + (size_t)warp * DH, lane);
    if (lane == 0) g_csq[warp] = s;
}

__global__ void xsq_kernel(const float* __restrict__ x) {
    int warp = (blockIdx.x * blockDim.x + threadIdx.x) >> 5;
    int lane = threadIdx.x & 31;
    if (warp >= N_TOK * NHEAD) return;
    float s = rowsq_xla(x + (size_t)warp * DH, lane);
    if (lane == 0) g_xsq[warp] = s;
}

__global__ void zero_loss_kernel(float* p) { p[0] = 0.f; }

// ---------------- Phase A: tf32 tensor screen, 32x64 warp tiles, 16 warps ----------------
// 512 thr / 16 warps: wm = warp>>2 (0..3), wn = warp&3 (0..3); warp tile 32 tok x 64 codes.
// XBuf: 128 tok x 256 d in a-fragment order (128 KB), staged once.
// CBuf: double-buffered b-fragment tiles for one 16-d half-chunk (2 x 16 KB).
__global__ __launch_bounds__(512, 1)
void vq_screen(const float* __restrict__ x, const float* __restrict__ cb) {
    extern __shared__ float dsm[];
    float* XBuf = dsm;                 // 32768 floats
    float* CBuf = dsm + 32768;         // 2 * 4096 floats

    __shared__ unsigned tokmin[128];
    __shared__ int cnt[128];
    __shared__ int cand[128][16];

    const int h    = blockIdx.y;
    const int tok0 = blockIdx.x * 128;
    const int tid  = threadIdx.x;
    const int warp = tid >> 5, lane = tid & 31;
    const int wm   = warp >> 2, wn = warp & 3;

    const float* xbase = x  + (size_t)tok0 * 1024 + h * DH;
    const float* cbase = cb + (size_t)h * NCODE * DH;

    if (tid < 128) { tokmin[tid] = 0x7F800000u; cnt[tid] = 0; }
    for (int i = tid; i < 128 * 16; i += 512) (&cand[0][0])[i] = 0;

    // ---- stage ALL of X into a-fragment layout (once; verified mapping) ----
    {
        int t  = tid >> 2;                 // token 0..127
        int r  = t & 15, tgs = t >> 4;
        const float* xrow = xbase + (size_t)t * 1024;
        int dbase = (tid & 3) * 64;
#pragma unroll
        for (int q = 0; q < 16; q++) {
            int d0 = dbase + q * 4;
            float4 v = *(const float4*)(xrow + d0);
            int kc8 = d0 >> 3;
            int c8  = d0 & 7;              // 0 or 4
            int slot = (r >> 3) + ((c8 >> 2) << 1);
            float* bp = XBuf + (size_t)((tgs * 32 + kc8) * 32) * 4;
            int lb = (r & 7) * 4;
            bp[(lb + 0) * 4 + slot] = to_tf32(v.x);
            bp[(lb + 1) * 4 + slot] = to_tf32(v.y);
            bp[(lb + 2) * 4 + slot] = to_tf32(v.z);
            bp[(lb + 3) * 4 + slot] = to_tf32(v.w);
        }
    }

    // per-thread C staging coords: i-th fragment F = tid + i*512 (verified mapping)
    int coff0[2];
#pragma unroll
    for (int i = 0; i < 2; i++) {
        int F  = tid + i * 512;
        int tl = F >> 5, l = F & 31;
        int p   = tl >> 4;
        int wnS = (tl >> 2) & 3;
        int npS = tl & 3;
        int n0  = wnS * 64 + npS * 16 + (l >> 2);
        coff0[i] = n0 * DH + p * 8 + (l & 3);
    }

    // xsq for my 4 token rows (2 m16 tiles x {row, row+8})
    float xsq0[2], xsq1[2];
#pragma unroll
    for (int mt = 0; mt < 2; mt++) {
        int t0 = wm * 32 + mt * 16 + (lane >> 2);
        xsq0[mt] = g_xsq[(size_t)(tok0 + t0) * NHEAD + h];
        xsq1[mt] = g_xsq[(size_t)(tok0 + t0 + 8) * NHEAD + h];
    }

    float acc[2][8][4];   // [mt][nt = np*2+tile][comp]
#pragma unroll
    for (int mt = 0; mt < 2; mt++)
#pragma unroll
        for (int nt = 0; nt < 8; nt++)
#pragma unroll
            for (int c = 0; c < 4; c++) acc[mt][nt][c] = 0.f;

    // prologue: LDG fragments for idx 0 (cbi=0, hc=0)
    float4 cr[2];
#pragma unroll
    for (int i = 0; i < 2; i++) {
        const float* p0 = cbase + coff0[i];
        cr[i].x = p0[0];
        cr[i].y = p0[4];
        cr[i].z = p0[2048];        // n0+8 row
        cr[i].w = p0[2048 + 4];
    }

    for (int idx = 0; idx < 64; idx++) {
        const int cbi = idx >> 4;
        const int hc  = idx & 15;
        const int b   = idx & 1;

        // STS: one conflict-free STS.128 per fragment
        {
            float4* cp = (float4*)(CBuf + b * 4096);
#pragma unroll
            for (int i = 0; i < 2; i++) {
                float4 w;
                w.x = to_tf32(cr[i].x); w.y = to_tf32(cr[i].y);
                w.z = to_tf32(cr[i].z); w.w = to_tf32(cr[i].w);
                cp[tid + i * 512] = w;
            }
        }
        // issue next LDGs early (overlap with barrier + MMA)
        if (idx < 63) {
            int idn = idx + 1;
            const float* base = cbase + (size_t)(idn >> 4) * 256 * DH + (idn & 15) * 16;
#pragma unroll
            for (int i = 0; i < 2; i++) {
                const float* p0 = base + coff0[i];
                cr[i].x = p0[0];
                cr[i].y = p0[4];
                cr[i].z = p0[2048];
                cr[i].w = p0[2048 + 4];
            }
        }
        __syncthreads();

        // MMA: 2 k8-steps, 2 a-frags x 4 b-float4s -> 16 HMMA per p
#pragma unroll
        for (int p = 0; p < 2; p++) {
            float4 av[2];
#pragma unroll
            for (int mt = 0; mt < 2; mt++)
                av[mt] = ((const float4*)XBuf)[((wm * 2 + mt) * 32 + hc * 2 + p) * 32 + lane];
#pragma unroll
            for (int np = 0; np < 4; np++) {
                float4 bv = ((const float4*)(CBuf + b * 4096))[(p * 16 + wn * 4 + np) * 32 + lane];
                uint32_t b0 = __float_as_uint(bv.x), b1 = __float_as_uint(bv.y);
                uint32_t b2 = __float_as_uint(bv.z), b3 = __float_as_uint(bv.w);
#pragma unroll
                for (int mt = 0; mt < 2; mt++) {
                    uint32_t a0 = __float_as_uint(av[mt].x), a1 = __float_as_uint(av[mt].y);
                    uint32_t a2 = __float_as_uint(av[mt].z), a3 = __float_as_uint(av[mt].w);
                    asm volatile(
                        "mma.sync.aligned.m16n8k8.row.col.f32.tf32.tf32.f32 "
                        "{%0,%1,%2,%3}, {%4,%5,%6,%7}, {%8,%9}, {%0,%1,%2,%3};"
                        : "+f"(acc[mt][np * 2][0]), "+f"(acc[mt][np * 2][1]),
                          "+f"(acc[mt][np * 2][2]), "+f"(acc[mt][np * 2][3])
                        : "r"(a0), "r"(a1), "r"(a2), "r"(a3), "r"(b0), "r"(b1));
                    asm volatile(
                        "mma.sync.aligned.m16n8k8.row.col.f32.tf32.tf32.f32 "
                        "{%0,%1,%2,%3}, {%4,%5,%6,%7}, {%8,%9}, {%0,%1,%2,%3};"
                        : "+f"(acc[mt][np * 2 + 1][0]), "+f"(acc[mt][np * 2 + 1][1]),
                          "+f"(acc[mt][np * 2 + 1][2]), "+f"(acc[mt][np * 2 + 1][3])
                        : "r"(a0), "r"(a1), "r"(a2), "r"(a3), "r"(b2), "r"(b3));
                }
            }
        }

        if (hc == 15) {
            // sweep 1: per-token thread-local min -> smem atomicMin
            float m0[2], m1[2];
#pragma unroll
            for (int mt = 0; mt < 2; mt++) { m0[mt] = 3.4e38f; m1[mt] = 3.4e38f; }
#pragma unroll
            for (int nt = 0; nt < 8; nt++)
#pragma unroll
                for (int c = 0; c < 2; c++) {
                    int k = cbi * 256 + wn * 64 + nt * 8 + 2 * (lane & 3) + c;
                    float csqv = g_csq[h * NCODE + k];
#pragma unroll
                    for (int mt = 0; mt < 2; mt++) {
                        m0[mt] = fminf(m0[mt], xsq0[mt] + csqv - 2.f * acc[mt][nt][c]);
                        m1[mt] = fminf(m1[mt], xsq1[mt] + csqv - 2.f * acc[mt][nt][c + 2]);
                    }
                }
#pragma unroll
            for (int mt = 0; mt < 2; mt++) {
                int t0 = wm * 32 + mt * 16 + (lane >> 2);
                atomicMin(&tokmin[t0], __float_as_uint(m0[mt]));
                atomicMin(&tokmin[t0 + 8], __float_as_uint(m1[mt]));
            }
            __syncthreads();

            // sweep 2: collect candidates within EPS of running min
            float th0[2], th1[2];
#pragma unroll
            for (int mt = 0; mt < 2; mt++) {
                int t0 = wm * 32 + mt * 16 + (lane >> 2);
                th0[mt] = __uint_as_float(tokmin[t0]) + EPS;
                th1[mt] = __uint_as_float(tokmin[t0 + 8]) + EPS;
            }
#pragma unroll
            for (int nt = 0; nt < 8; nt++)
#pragma unroll
                for (int c = 0; c < 2; c++) {
                    int k = cbi * 256 + wn * 64 + nt * 8 + 2 * (lane & 3) + c;
                    float csqv = g_csq[h * NCODE + k];
#pragma unroll
                    for (int mt = 0; mt < 2; mt++) {
                        int t0 = wm * 32 + mt * 16 + (lane >> 2);
                        float d0 = xsq0[mt] + csqv - 2.f * acc[mt][nt][c];
                        float d1 = xsq1[mt] + csqv - 2.f * acc[mt][nt][c + 2];
                        if (d0 <= th0[mt]) {
                            int pos = atomicAdd(&cnt[t0], 1);
                            if (pos < 16) cand[t0][pos] = k;
                        }
                        if (d1 <= th1[mt]) {
                            int pos = atomicAdd(&cnt[t0 + 8], 1);
                            if (pos < 16) cand[t0 + 8][pos] = k;
                        }
                    }
                }
            __syncthreads();

#pragma unroll
            for (int mt = 0; mt < 2; mt++)
#pragma unroll
                for (int nt = 0; nt < 8; nt++)
#pragma unroll
                    for (int c = 0; c < 4; c++) acc[mt][nt][c] = 0.f;
        }
    }

    if (tid < 128) {
        int tokg = h * N_TOK + tok0 + tid;
        g_cnt[tokg] = cnt[tid];
#pragma unroll
        for (int j = 0; j < 16; j++) g_cand[(size_t)tokg * 16 + j] = cand[tid][j];
    }
}

// ---------------- Phase B: exact rescore (FROZEN serial chain per candidate) ----------------
__global__ __launch_bounds__(256)
void vq_rescore(const float* __restrict__ x, const float* __restrict__ cb) {
    const int h    = blockIdx.y;
    const int tok  = blockIdx.x * 8 + (threadIdx.x >> 5);
    const int lane = threadIdx.x & 31;

    const int   tokg = h * N_TOK + tok;
    const int   n    = g_cnt[tokg];
    const float xsqv = g_xsq[(size_t)tok * NHEAD + h];
    const float* xrow = x + ((size_t)tok * NHEAD + h) * DH;

    float bv = 3.4e38f;
    int   bi = 0x7FFFFFFF;

    auto score = [&](int k) {
        const float* crow = cb + ((size_t)h * NCODE + k) * DH;
        float a = 0.f;
#pragma unroll 8
        for (int d4 = 0; d4 < DH / 4; d4++) {
            float4 xv = *(const float4*)(xrow + d4 * 4);
            float4 cv = *(const float4*)(crow + d4 * 4);
            a = fmaf(xv.x, cv.x, a);
            a = fmaf(xv.y, cv.y, a);
            a = fmaf(xv.z, cv.z, a);
            a = fmaf(xv.w, cv.w, a);
        }
        float t1   = __fadd_rn(xsqv, g_csq[h * NCODE + k]);
        float dist = __fsub_rn(t1, __fmul_rn(2.f, a));
        if (dist < bv || (dist == bv && k < bi)) { bv = dist; bi = k; }
    };

    if (n <= 16) {
        if (lane < n) score(g_cand[(size_t)tokg * 16 + lane]);
    } else {
        for (int k = lane; k < NCODE; k += 32) score(k);
    }

#pragma unroll
    for (int off = 16; off > 0; off >>= 1) {
        float vo = __shfl_down_sync(0xFFFFFFFFu, bv, off);
        int   io = __shfl_down_sync(0xFFFFFFFFu, bi, off);
        if (vo < bv || (vo == bv && io < bi)) { bv = vo; bi = io; }
    }
    if (lane == 0) g_idx[tokg] = bi;
}

// ---------------- epilogue: gather + straight-through + loss ----------------
#define TME 64
__global__ __launch_bounds__(256)
void epilogue_kernel(const float* __restrict__ x, const float* __restrict__ cb,
                     float* __restrict__ qout, float* loss_out) {
    __shared__ float lred[8];

    const int h    = blockIdx.y;
    const int tok0 = blockIdx.x * TME;
    const int tid  = threadIdx.x;
    const float* xbase = x  + (size_t)tok0 * 1024 + h * DH;
    const float* cbase = cb + (size_t)h * NCODE * DH;

    float lsum = 0.f;
#pragma unroll 4
    for (int g = tid; g < TME * (DH / 4); g += 256) {
        int t  = g >> 6;
        int dq = g & 63;
        int k  = g_idx[h * N_TOK + tok0 + t];
        float4 c  = *(const float4*)(cbase + (size_t)k * DH + dq * 4);
        float4 xv = *(const float4*)(xbase + (size_t)t * 1024 + dq * 4);
        float dx0 = c.x - xv.x, dx1 = c.y - xv.y, dx2 = c.z - xv.z, dx3 = c.w - xv.w;
        lsum += dx0 * dx0 + dx1 * dx1 + dx2 * dx2 + dx3 * dx3;
        float* o = qout + (size_t)(tok0 + t) * 1024 + h * DH + dq * 4;  // 4B-aligned only
        o[0] = xv.x + dx0;
        o[1] = xv.y + dx1;
        o[2] = xv.z + dx2;
        o[3] = xv.w + dx3;
    }

    if (loss_out) {
#pragma unroll
        for (int off = 16; off > 0; off >>= 1)
            lsum += __shfl_down_sync(0xFFFFFFFFu, lsum, off);
        if ((tid & 31) == 0) lred[tid >> 5] = lsum;
        __syncthreads();
        if (tid == 0) {
            float s = 0.f;
#pragma unroll
            for (int w = 0; w < 8; w++) s += lred[w];
            atomicAdd(loss_out, s * (0.25f / (float)((size_t)N_TOK * 1024)));
        }
    }
}

extern "C" void kernel_launch(void* const* d_in, const int* in_sizes, int n_in,
                              void* d_out, int out_size) {
    const float* x  = (const float*)d_in[0];
    const float* cb = (const float*)d_in[1];
    float* out = (float*)d_out;

    const long long qelems = (long long)N_TOK * 1024;
    int has_loss = (out_size == (int)(qelems + 1)) ? 1 : 0;
    float* qout     = out + (has_loss ? 1 : 0);
    float* loss_out = has_loss ? out : (float*)0;

    static int smem_set = 0;
    const int DSMEM = (32768 + 2 * 4096) * 4;   // 160 KB
    if (!smem_set) {
        cudaFuncSetAttribute(vq_screen, cudaFuncAttributeMaxDynamicSharedMemorySize, DSMEM);
        smem_set = 1;
    }

    csq_kernel<<<(NHEAD * NCODE * 32 + 255) / 256, 256>>>(cb);
    xsq_kernel<<<(N_TOK * NHEAD * 32 + 255) / 256, 256>>>(x);
    if (has_loss) zero_loss_kernel<<<1, 1>>>(out);

    dim3 sgrid(N_TOK / 128, NHEAD);
    vq_screen<<<sgrid, 512, DSMEM>>>(x, cb);

    dim3 rgrid(N_TOK / 8, NHEAD);
    vq_rescore<<<rgrid, 256>>>(x, cb);

    dim3 egrid(N_TOK / TME, NHEAD);
    epilogue_kernel<<<egrid, 256>>>(x, cb, qout, loss_out);
}